// round 2
// baseline (speedup 1.0000x reference)
#include <cuda_runtime.h>

#define B_ 4
#define L_ 1024
#define H_ 8
#define E_ 64
#define PLANE (1024*1024)

// 128 MB scratch each (zero-initialized .bss). buf1's above-diagonal region is
// NEVER written by any kernel, so it stays 0 deterministically across replays.
__device__ float g_buf1[(size_t)B_*H_*L_*L_];
__device__ float g_buf2[(size_t)B_*H_*L_*L_];

// ---------------------------------------------------------------------------
// Pass A: S1[b,h,l,s] = (Q.K^T)*scale, causal zeroed within diagonal tiles.
// Fully-masked tiles are SKIPPED (buf1 stays .bss zero there forever).
// grid (16,16,32), block (16,16). 64x64 tile, 4x4 per thread.
// ---------------------------------------------------------------------------
__global__ void qk_kernel(const float* __restrict__ q, const float* __restrict__ k)
{
    const int bh = blockIdx.z;
    const int b  = bh >> 3, h = bh & 7;
    const int l0 = blockIdx.y << 6, s0 = blockIdx.x << 6;
    if (s0 > l0 + 63) return;   // fully masked: never written, stays zero

    const int tx = threadIdx.x, ty = threadIdx.y;
    const int tid = ty * 16 + tx;
    float* outp = g_buf1 + (size_t)bh * PLANE;

    __shared__ float Qs[64][65];
    __shared__ float Ks[64][65];
    const float* qb = q + (size_t)b * L_ * (H_ * E_) + h * E_;
    const float* kb = k + (size_t)b * L_ * (H_ * E_) + h * E_;

    #pragma unroll
    for (int i = 0; i < 4; i++) {
        int row = (tid >> 4) + (i << 4);
        int c   = (tid & 15) << 2;
        float4 qv = *(const float4*)&qb[(size_t)(l0 + row) * 512 + c];
        Qs[row][c] = qv.x; Qs[row][c+1] = qv.y; Qs[row][c+2] = qv.z; Qs[row][c+3] = qv.w;
        float4 kv = *(const float4*)&kb[(size_t)(s0 + row) * 512 + c];
        Ks[row][c] = kv.x; Ks[row][c+1] = kv.y; Ks[row][c+2] = kv.z; Ks[row][c+3] = kv.w;
    }
    __syncthreads();

    float acc[4][4];
    #pragma unroll
    for (int i = 0; i < 4; i++)
        #pragma unroll
        for (int j = 0; j < 4; j++) acc[i][j] = 0.f;

    #pragma unroll
    for (int e = 0; e < 64; e++) {
        float qv[4], kv[4];
        #pragma unroll
        for (int i = 0; i < 4; i++) qv[i] = Qs[ty * 4 + i][e];
        #pragma unroll
        for (int j = 0; j < 4; j++) kv[j] = Ks[tx * 4 + j][e];
        #pragma unroll
        for (int i = 0; i < 4; i++)
            #pragma unroll
            for (int j = 0; j < 4; j++) acc[i][j] += qv[i] * kv[j];
    }

    const float scale = 0.125f;  // 1/sqrt(64)
    #pragma unroll
    for (int i = 0; i < 4; i++) {
        int l = l0 + ty * 4 + i;
        int sb = s0 + tx * 4;
        float4 r;
        r.x = (sb + 0 <= l) ? acc[i][0] * scale : 0.f;
        r.y = (sb + 1 <= l) ? acc[i][1] * scale : 0.f;
        r.z = (sb + 2 <= l) ? acc[i][2] * scale : 0.f;
        r.w = (sb + 3 <= l) ? acc[i][3] * scale : 0.f;
        *(float4*)&outp[(size_t)l * 1024 + sb] = r;
    }
}

// ---------------------------------------------------------------------------
// Pass B: S2[b,g,l,s] = sum_h wpsm[g,h] * conv3x3(S1[b,h])[l,s]
// grid (32,32,4), early-exit above diagonal. block 256.
// ---------------------------------------------------------------------------
__global__ void convmix_kernel(const float* __restrict__ mta_k, const float* __restrict__ wpsm)
{
    if (blockIdx.x > blockIdx.y) return;
    const int st = blockIdx.x << 5, lt = blockIdx.y << 5, b = blockIdx.z;
    const int tid = threadIdx.x;

    __shared__ float sm[8][34][35];
    __shared__ float kk[8][9];
    __shared__ float wm[64];
    if (tid < 72) kk[tid / 9][tid % 9] = mta_k[tid];
    if (tid < 64) wm[tid] = wpsm[tid];

    const float* inb = g_buf1 + (size_t)b * 8 * PLANE;
    for (int idx = tid; idx < 8 * 34 * 34; idx += 256) {
        int h = idx / (34 * 34);
        int r = (idx / 34) % 34;
        int c = idx % 34;
        int gl = lt - 2 + r, gs = st - 1 + c;
        float v = 0.f;
        if (gl >= 0 && gs >= 0 && gs < 1024)
            v = inb[(size_t)h * PLANE + (size_t)gl * 1024 + gs];
        sm[h][r][c] = v;
    }
    __syncthreads();

    float* outb = g_buf2 + (size_t)b * 8 * PLANE;
    for (int p = tid; p < 1024; p += 256) {
        int li = p >> 5, si = p & 31;
        float c[8];
        #pragma unroll
        for (int h = 0; h < 8; h++) {
            float a = 0.f;
            #pragma unroll
            for (int i = 0; i < 3; i++)
                #pragma unroll
                for (int j = 0; j < 3; j++)
                    a += kk[h][i * 3 + j] * sm[h][li + i][si + j];
            c[h] = a;
        }
        size_t off = (size_t)(lt + li) * 1024 + (st + si);
        #pragma unroll
        for (int g = 0; g < 8; g++) {
            float a = 0.f;
            #pragma unroll
            for (int h = 0; h < 8; h++) a += wm[g * 8 + h] * c[h];
            outb[(size_t)g * PLANE + off] = a;
        }
    }
}

// ---------------------------------------------------------------------------
// Pass C: row softmax over s in [0, l]. Reads buf2, writes buf1 (only s<=l;
// s>l region of buf1 remains zero — required by Pass E's conv halo).
// grid 32768, block 128.
// ---------------------------------------------------------------------------
__global__ void softmax_kernel()
{
    const int row = blockIdx.x;
    const int l = row & 1023;
    const int n = l + 1;
    const float* rp = g_buf2 + (size_t)row * 1024;
    float* op = g_buf1 + (size_t)row * 1024;
    const int tid = threadIdx.x;
    const int wid = tid >> 5, lane = tid & 31;

    float v[8];
    float mx = -1e30f;
    #pragma unroll
    for (int i = 0; i < 8; i++) {
        int s = tid + (i << 7);
        v[i] = (s < n) ? rp[s] : -1e30f;
        mx = fmaxf(mx, v[i]);
    }
    #pragma unroll
    for (int o = 16; o; o >>= 1) mx = fmaxf(mx, __shfl_xor_sync(0xffffffffu, mx, o));

    __shared__ float smax[4];
    __shared__ float ssum[4];
    if (lane == 0) smax[wid] = mx;
    __syncthreads();
    if (wid == 0) {
        float m = (lane < 4) ? smax[lane] : -1e30f;
        #pragma unroll
        for (int o = 2; o; o >>= 1) m = fmaxf(m, __shfl_xor_sync(0xffffffffu, m, o));
        if (lane == 0) smax[0] = m;
    }
    __syncthreads();
    mx = smax[0];

    float sum = 0.f;
    #pragma unroll
    for (int i = 0; i < 8; i++) {
        int s = tid + (i << 7);
        if (s < n) { v[i] = __expf(v[i] - mx); sum += v[i]; }
    }
    #pragma unroll
    for (int o = 16; o; o >>= 1) sum += __shfl_xor_sync(0xffffffffu, sum, o);
    if (lane == 0) ssum[wid] = sum;
    __syncthreads();
    if (wid == 0) {
        float m = (lane < 4) ? ssum[lane] : 0.f;
        #pragma unroll
        for (int o = 2; o; o >>= 1) m += __shfl_xor_sync(0xffffffffu, m, o);
        if (lane == 0) ssum[0] = m;
    }
    __syncthreads();
    float inv = 1.0f / ssum[0];

    #pragma unroll
    for (int i = 0; i < 8; i++) {
        int s = tid + (i << 7);
        if (s < n) op[s] = v[i] * inv;
    }
}

// ---------------------------------------------------------------------------
// Pass E (FUSED conv-after + head-pair mix + AV GEMM):
// For head pair (2g, 2g+1):
//   P_j = conv3x3_after(A[2g+j]); causal-zeroed
//   A2_k = P_0*hk[g,0,k] + P_1*hk[g,1,k]
//   out[2g+k, l, :] = sum_s A2_k[l,s] * V[s, 2g+k, :]
// One block: 64 l-rows x 64 e x 2 heads. Loops s-tiles 0..l0.
// Dynamic smem: raw A halo (2x66x67), mixed tiles (2x64x65), V tiles (2x64x65).
// grid (16, 16) = (l-tile, b*4+gpair), block (16,16).
// ---------------------------------------------------------------------------
#define RAW_STRIDE 67
#define RAW_OFF    0
#define CS_OFF     (2*66*67)
#define VS_OFF     (CS_OFF + 2*64*65)
#define SMEM_FLOATS (VS_OFF + 2*64*65)

__global__ void av_fused_kernel(const float* __restrict__ v,
                                const float* __restrict__ mta_after,
                                const float* __restrict__ head_k,
                                float* __restrict__ out)
{
    extern __shared__ float smem[];
    float* raw = smem + RAW_OFF;   // [2][66][67]
    float* cs  = smem + CS_OFF;    // [2][64][65] mixed A2
    float* vs  = smem + VS_OFF;    // [2][64][65]

    const int pg = blockIdx.y;
    const int b  = pg >> 2, g = pg & 3;
    const int l0 = blockIdx.x << 6;
    const int tx = threadIdx.x, ty = threadIdx.y;
    const int tid = ty * 16 + tx;

    __shared__ float kk[2][9];
    __shared__ float hk[4];
    if (tid < 18) kk[tid / 9][tid % 9] = mta_after[(2 * g) * 9 + tid];
    if (tid < 4)  hk[tid] = head_k[g * 4 + tid];

    const float* A0 = g_buf1 + (size_t)(b * 8 + 2 * g) * PLANE;
    const float* A1 = A0 + PLANE;
    const float* vb = v + (size_t)b * L_ * 512;

    float acc0[4][4], acc1[4][4];
    #pragma unroll
    for (int i = 0; i < 4; i++)
        #pragma unroll
        for (int j = 0; j < 4; j++) { acc0[i][j] = 0.f; acc1[i][j] = 0.f; }

    for (int s0 = 0; s0 <= l0; s0 += 64) {
        // ---- load raw A halo tiles (66 rows x 66 cols) for both heads ----
        for (int idx = tid; idx < 2 * 66 * 66; idx += 256) {
            int h = idx / (66 * 66);
            int r = (idx / 66) % 66;
            int c = idx % 66;
            int gl = l0 - 2 + r, gs = s0 - 1 + c;
            float val = 0.f;
            if (gl >= 0 && gs >= 0 && gs < 1024) {
                const float* Ab = h ? A1 : A0;
                val = Ab[(size_t)gl * 1024 + gs];
            }
            raw[(h * 66 + r) * RAW_STRIDE + c] = val;
        }
        // ---- load V tiles for heads 2g, 2g+1 ----
        for (int idx = tid; idx < 2 * 64 * 16; idx += 256) {
            int h = idx / (64 * 16);
            int r = (idx / 16) % 64;
            int c = (idx % 16) << 2;
            float4 vv = *(const float4*)&vb[(size_t)(s0 + r) * 512 + (2 * g + h) * 64 + c];
            float* dst = &vs[(h * 64 + r) * 65 + c];
            dst[0] = vv.x; dst[1] = vv.y; dst[2] = vv.z; dst[3] = vv.w;
        }
        __syncthreads();

        // ---- conv3x3 both heads + causal zero + head-pair mix -> cs ----
        for (int p = tid; p < 4096; p += 256) {
            int li = p >> 6, si = p & 63;
            float c0 = 0.f, c1 = 0.f;
            #pragma unroll
            for (int i = 0; i < 3; i++)
                #pragma unroll
                for (int j = 0; j < 3; j++) {
                    float r0 = raw[(0 * 66 + li + i) * RAW_STRIDE + si + j];
                    float r1 = raw[(1 * 66 + li + i) * RAW_STRIDE + si + j];
                    c0 += kk[0][i * 3 + j] * r0;
                    c1 += kk[1][i * 3 + j] * r1;
                }
            bool cz = (s0 + si) <= (l0 + li);
            cs[(0 * 64 + li) * 65 + si] = cz ? (c0 * hk[0] + c1 * hk[2]) : 0.f;
            cs[(1 * 64 + li) * 65 + si] = cz ? (c0 * hk[1] + c1 * hk[3]) : 0.f;
        }
        __syncthreads();

        // ---- GEMM: acc_k += cs[k] @ vs[k] ----
        #pragma unroll
        for (int kx = 0; kx < 64; kx++) {
            float a0[4], a1[4], v0[4], v1[4];
            #pragma unroll
            for (int i = 0; i < 4; i++) {
                a0[i] = cs[(0 * 64 + ty * 4 + i) * 65 + kx];
                a1[i] = cs[(1 * 64 + ty * 4 + i) * 65 + kx];
            }
            #pragma unroll
            for (int j = 0; j < 4; j++) {
                v0[j] = vs[(0 * 64 + kx) * 65 + tx * 4 + j];
                v1[j] = vs[(1 * 64 + kx) * 65 + tx * 4 + j];
            }
            #pragma unroll
            for (int i = 0; i < 4; i++)
                #pragma unroll
                for (int j = 0; j < 4; j++) {
                    acc0[i][j] += a0[i] * v0[j];
                    acc1[i][j] += a1[i] * v1[j];
                }
        }
        __syncthreads();
    }

    #pragma unroll
    for (int i = 0; i < 4; i++) {
        int l = l0 + ty * 4 + i;
        int e = tx * 4;
        size_t base = ((size_t)(b * L_ + l) * H_) * E_;
        float4 r0 = make_float4(acc0[i][0], acc0[i][1], acc0[i][2], acc0[i][3]);
        float4 r1 = make_float4(acc1[i][0], acc1[i][1], acc1[i][2], acc1[i][3]);
        *(float4*)&out[base + (2 * blockIdx.y % 8 == 0 ? 0 : 0) + (size_t)(2 * (blockIdx.y & 3)) * E_ + e] = r0;
        *(float4*)&out[base + (size_t)(2 * (blockIdx.y & 3) + 1) * E_ + e] = r1;
    }
}

// ---------------------------------------------------------------------------
extern "C" void kernel_launch(void* const* d_in, const int* in_sizes, int n_in,
                              void* d_out, int out_size)
{
    const float* q         = (const float*)d_in[0];
    const float* k         = (const float*)d_in[1];
    const float* v         = (const float*)d_in[2];
    const float* mta       = (const float*)d_in[3];
    const float* mta_after = (const float*)d_in[4];
    const float* head_k    = (const float*)d_in[5];
    const float* wpsm      = (const float*)d_in[6];
    float* out = (float*)d_out;

    dim3 bA(16, 16);
    dim3 gA(16, 16, 32);
    qk_kernel<<<gA, bA>>>(q, k);

    dim3 gB(32, 32, 4);
    convmix_kernel<<<gB, 256>>>(mta, wpsm);

    softmax_kernel<<<32768, 128>>>();

    size_t smem_bytes = (size_t)SMEM_FLOATS * sizeof(float);
    cudaFuncSetAttribute(av_fused_kernel, cudaFuncAttributeMaxDynamicSharedMemorySize,
                         (int)smem_bytes);
    dim3 gE(16, 16);
    av_fused_kernel<<<gE, bA, smem_bytes>>>(v, mta_after, head_k, out);
}